// round 3
// baseline (speedup 1.0000x reference)
#include <cuda_runtime.h>

// PatchEmbed: gather KNN -> center-subtract -> MLP(3->64->128->256, relu, relu, none) -> max over K
// Round 3: register-blocked layers 2/3 (4 channels x dot-slice per thread, quad shfl-reduce)
// to cut LDS instruction traffic 4x (R2 bottleneck: L1TEX 88% vs fma 29%).

constexpr int Bb = 8;
constexpr int Nn = 16384;
constexpr int Mc = 2048;
constexpr int Kn = 32;
constexpr int C1 = 64;
constexpr int C2 = 128;
constexpr int C3 = 256;

__device__ __forceinline__ unsigned long long pfma2(unsigned long long a,
                                                    unsigned long long b,
                                                    unsigned long long c) {
    unsigned long long d;
    asm("fma.rn.f32x2 %0, %1, %2, %3;" : "=l"(d) : "l"(a), "l"(b), "l"(c));
    return d;
}

__device__ __forceinline__ float2 u2f2(unsigned long long u) {
    float2 f;
    asm("mov.b64 {%0, %1}, %2;" : "=f"(f.x), "=f"(f.y) : "l"(u));
    return f;
}

__global__ __launch_bounds__(256, 1)
void patch_embed_kernel(const float* __restrict__ xyz,
                        const float* __restrict__ centers,
                        const int*   __restrict__ idx,
                        const float* __restrict__ W1, const float* __restrict__ b1,
                        const float* __restrict__ W2, const float* __restrict__ b2,
                        const float* __restrict__ W3, const float* __restrict__ b3,
                        float* __restrict__ out) {
    __shared__ __align__(16) float ls[Kn][3];
    __shared__ __align__(16) float h1s[Kn][C1];   // 8 KB
    __shared__ __align__(16) float h2s[Kn][C2];   // 16 KB

    const int bm  = blockIdx.x;
    const int b   = bm >> 11;       // / 2048
    const int tid = threadIdx.x;

    // ---- gather neighbors + center subtract ----
    if (tid < Kn) {
        const int   id = idx[(size_t)bm * Kn + tid];
        const float* p = xyz + ((size_t)b * Nn + id) * 3;
        const float* c = centers + (size_t)bm * 3;
        ls[tid][0] = p[0] - c[0];
        ls[tid][1] = p[1] - c[1];
        ls[tid][2] = p[2] - c[2];
    }
    __syncthreads();

    // ---- layer 1: h1[k][c] = relu(W1[c] . local[k] + b1[c]) ----
#pragma unroll
    for (int rr = 0; rr < 8; rr++) {
        const int o = tid + rr * 256;
        const int k = o >> 6;
        const int c = o & (C1 - 1);
        const float lx = ls[k][0], ly = ls[k][1], lz = ls[k][2];
        float v = fmaf(__ldg(&W1[c * 3 + 0]), lx,
                  fmaf(__ldg(&W1[c * 3 + 1]), ly,
                  fmaf(__ldg(&W1[c * 3 + 2]), lz, __ldg(&b1[c]))));
        h1s[k][c] = fmaxf(v, 0.0f);
    }
    __syncthreads();

    // ---- layer 2: h2[k][c2] = relu(W2[c2] . h1[k] + b2[c2]) ----
    // Quad of lanes: q2 in [0,32) -> 4 channels; lane r in quad -> 16-float slice of C1.
    // Two thread halves (kg) split the 32 k's. Rotated slice loads avoid bank conflicts.
    {
        const int kg = tid >> 7;           // 0..1
        const int t7 = tid & 127;
        const int q  = t7 >> 2;            // 0..31 -> channels 4q..4q+3
        const int r  = t7 & 3;             // slice [16r, 16r+16)

        ulonglong2 w2r[4][4];
#pragma unroll
        for (int j = 0; j < 4; j++) {
            const ulonglong2* row = reinterpret_cast<const ulonglong2*>(W2 + (size_t)(4 * q + j) * C1);
#pragma unroll
            for (int i = 0; i < 4; i++)
                w2r[j][i] = row[4 * r + ((i + r) & 3)];
        }
        const int   myc   = 4 * q + r;
        const float bias2 = __ldg(&b2[myc]);

#pragma unroll 1
        for (int kk = 0; kk < 16; kk++) {
            const int k = kg * 16 + kk;
            const ulonglong2* hrow = reinterpret_cast<const ulonglong2*>(&h1s[k][0]);
            ulonglong2 hv[4];
#pragma unroll
            for (int i = 0; i < 4; i++)
                hv[i] = hrow[4 * r + ((i + r) & 3)];

            float t0, t1, t2, t3;
#pragma unroll
            for (int j = 0; j < 4; j++) {
                unsigned long long a = 0ull, bb = 0ull;
#pragma unroll
                for (int i = 0; i < 4; i++) {
                    a  = pfma2(hv[i].x, w2r[j][i].x, a);
                    bb = pfma2(hv[i].y, w2r[j][i].y, bb);
                }
                const float2 fa = u2f2(a), fb = u2f2(bb);
                float s = (fa.x + fa.y) + (fb.x + fb.y);
                s += __shfl_xor_sync(0xffffffffu, s, 1);
                s += __shfl_xor_sync(0xffffffffu, s, 2);
                if (j == 0) t0 = s; else if (j == 1) t1 = s;
                else if (j == 2) t2 = s; else t3 = s;
            }
            const float sel = (r == 0) ? t0 : (r == 1) ? t1 : (r == 2) ? t2 : t3;
            h2s[k][myc] = fmaxf(sel + bias2, 0.0f);
        }
    }
    __syncthreads();

    // ---- layer 3 + max over k ----
    // Quad q in [0,64) -> channels 4q..4q+3 (so channel == tid); lane r -> 32-float slice of C2.
    {
        const int q = tid >> 2;            // 0..63
        const int r = tid & 3;             // slice [32r, 32r+32)

        ulonglong2 w3r[4][8];
#pragma unroll
        for (int j = 0; j < 4; j++) {
            const ulonglong2* row = reinterpret_cast<const ulonglong2*>(W3 + (size_t)(4 * q + j) * C2);
#pragma unroll
            for (int i = 0; i < 8; i++)
                w3r[j][i] = row[8 * r + ((i + 2 * r) & 7)];
        }

        float vm0 = -1e30f, vm1 = -1e30f, vm2 = -1e30f, vm3 = -1e30f;

        const ulonglong2* hrow0 = reinterpret_cast<const ulonglong2*>(&h2s[0][0]);
        ulonglong2 hv[2][8];
#pragma unroll
        for (int i = 0; i < 8; i++)
            hv[0][i] = hrow0[8 * r + ((i + 2 * r) & 7)];

#pragma unroll 1
        for (int k = 0; k < Kn; k++) {
            const int cur = k & 1;
            if (k + 1 < Kn) {
                const ulonglong2* hrown = reinterpret_cast<const ulonglong2*>(&h2s[k + 1][0]);
#pragma unroll
                for (int i = 0; i < 8; i++)
                    hv[cur ^ 1][i] = hrown[8 * r + ((i + 2 * r) & 7)];
            }

#pragma unroll
            for (int j = 0; j < 4; j++) {
                unsigned long long a = 0ull, bb = 0ull;
#pragma unroll
                for (int i = 0; i < 8; i++) {
                    a  = pfma2(hv[cur][i].x, w3r[j][i].x, a);
                    bb = pfma2(hv[cur][i].y, w3r[j][i].y, bb);
                }
                const float2 fa = u2f2(a), fb = u2f2(bb);
                float s = (fa.x + fa.y) + (fb.x + fb.y);
                s += __shfl_xor_sync(0xffffffffu, s, 1);
                s += __shfl_xor_sync(0xffffffffu, s, 2);
                if (j == 0) vm0 = fmaxf(vm0, s);
                else if (j == 1) vm1 = fmaxf(vm1, s);
                else if (j == 2) vm2 = fmaxf(vm2, s);
                else vm3 = fmaxf(vm3, s);
            }
        }

        const float vms = (r == 0) ? vm0 : (r == 1) ? vm1 : (r == 2) ? vm2 : vm3;
        out[(size_t)bm * C3 + tid] = vms + __ldg(&b3[tid]);   // channel c3 == tid
    }
}

extern "C" void kernel_launch(void* const* d_in, const int* in_sizes, int n_in,
                              void* d_out, int out_size) {
    (void)in_sizes; (void)n_in; (void)out_size;
    const float* xyz     = (const float*)d_in[0];
    const float* centers = (const float*)d_in[1];
    const int*   idx     = (const int*)  d_in[2];
    const float* W1      = (const float*)d_in[3];
    const float* b1      = (const float*)d_in[4];
    const float* W2      = (const float*)d_in[5];
    const float* b2      = (const float*)d_in[6];
    const float* W3      = (const float*)d_in[7];
    const float* b3      = (const float*)d_in[8];
    float*       out     = (float*)d_out;

    patch_embed_kernel<<<Bb * Mc, 256>>>(xyz, centers, idx,
                                         W1, b1, W2, b2, W3, b3, out);
}

// round 4
// speedup vs baseline: 2.4376x; 2.4376x over previous
#include <cuda_runtime.h>

// PatchEmbed fused kernel, round 4.
// gather KNN -> center-subtract -> MLP(3->64->128->256, relu, relu, none) -> max over K=32
// P=4 points per CTA (amortizes per-CTA weight-register loads 4x),
// layer3: thread owns 2 channels {q, q+128} x half dot-slice; pair-shfl reduce;
// bank-rotated broadcast LDS. All math packed fma.rn.f32x2.

constexpr int Bb = 8;
constexpr int Nn = 16384;
constexpr int Mc = 2048;
constexpr int Kn = 32;
constexpr int C1 = 64;
constexpr int C2 = 128;
constexpr int C3 = 256;
constexpr int P  = 4;                    // points per CTA

// dynamic smem layout (floats): ls[P][Kn][4] | h1[P][Kn][C1] | h2[P][Kn][C2]
constexpr int LS_F  = P * Kn * 4;        // 512
constexpr int H1_F  = P * Kn * C1;       // 8192
constexpr int H2_F  = P * Kn * C2;       // 16384
constexpr int SMEM_F = LS_F + H1_F + H2_F;           // 25088 floats
constexpr int SMEM_BYTES = SMEM_F * 4;               // 100352 B

__device__ __forceinline__ unsigned long long pfma2(unsigned long long a,
                                                    unsigned long long b,
                                                    unsigned long long c) {
    unsigned long long d;
    asm("fma.rn.f32x2 %0, %1, %2, %3;" : "=l"(d) : "l"(a), "l"(b), "l"(c));
    return d;
}

__device__ __forceinline__ float2 u2f2(unsigned long long u) {
    float2 f;
    asm("mov.b64 {%0, %1}, %2;" : "=f"(f.x), "=f"(f.y) : "l"(u));
    return f;
}

__global__ __launch_bounds__(256, 1)
void patch_embed_kernel(const float* __restrict__ xyz,
                        const float* __restrict__ centers,
                        const int*   __restrict__ idx,
                        const float* __restrict__ W1, const float* __restrict__ b1,
                        const float* __restrict__ W2, const float* __restrict__ b2,
                        const float* __restrict__ W3, const float* __restrict__ b3,
                        float* __restrict__ out) {
    extern __shared__ float smem[];
    float* ls  = smem;                 // [P][Kn][4]
    float* h1s = smem + LS_F;          // [P][Kn][C1]
    float* h2s = smem + LS_F + H1_F;   // [P][Kn][C2]

    const int bm0 = blockIdx.x * P;    // first point of this CTA (all P share batch b)
    const int b   = bm0 >> 11;         // / Mc
    const int tid = threadIdx.x;

    // ---- gather neighbors + center subtract (P*Kn = 128 threads) ----
    if (tid < P * Kn) {
        const int p  = tid >> 5;
        const int k  = tid & 31;
        const int bm = bm0 + p;
        const int id = idx[(size_t)bm * Kn + k];
        const float* xp = xyz + ((size_t)b * Nn + id) * 3;
        const float* cp = centers + (size_t)bm * 3;
        float* lp = ls + (size_t)tid * 4;
        lp[0] = xp[0] - cp[0];
        lp[1] = xp[1] - cp[1];
        lp[2] = xp[2] - cp[2];
        lp[3] = 0.0f;
    }
    __syncthreads();

    // ---- layer 1: h1[p][k][c] = relu(W1[c].local + b1[c]); 8192 outs, 32/thread ----
#pragma unroll
    for (int it = 0; it < (P * Kn * C1) / 256; it++) {
        const int o  = tid + it * 256;
        const int pk = o >> 6;                 // p*Kn + k
        const int c  = o & (C1 - 1);
        const float4 lv = *reinterpret_cast<const float4*>(ls + (size_t)pk * 4);
        float v = fmaf(__ldg(&W1[c * 3 + 0]), lv.x,
                  fmaf(__ldg(&W1[c * 3 + 1]), lv.y,
                  fmaf(__ldg(&W1[c * 3 + 2]), lv.z, __ldg(&b1[c]))));
        h1s[(size_t)pk * C1 + c] = fmaxf(v, 0.0f);
    }
    __syncthreads();

    // ---- layer 2: h2[p][k][c2] = relu(W2[c2].h1[p][k] + b2[c2]) ----
    // thread -> (c2 = tid&127, kg = tid>>7); W2 row (64 floats) in regs, reused for P points.
    {
        const int c2 = tid & (C2 - 1);
        const int kg = tid >> 7;
        ulonglong2 w2r[16];
        const ulonglong2* w2g = reinterpret_cast<const ulonglong2*>(W2 + (size_t)c2 * C1);
#pragma unroll
        for (int i = 0; i < 16; i++) w2r[i] = w2g[i];
        const float bias2 = __ldg(&b2[c2]);

#pragma unroll 1
        for (int p = 0; p < P; p++) {
#pragma unroll 1
            for (int kk = 0; kk < 16; kk++) {
                const int k = kg * 16 + kk;
                const ulonglong2* hrow =
                    reinterpret_cast<const ulonglong2*>(h1s + ((size_t)p * Kn + k) * C1);
                unsigned long long a0 = 0ull, a1 = 0ull;
#pragma unroll
                for (int i = 0; i < 16; i++) {
                    const ulonglong2 h = hrow[i];      // broadcast LDS.128
                    a0 = pfma2(h.x, w2r[i].x, a0);
                    a1 = pfma2(h.y, w2r[i].y, a1);
                }
                const float2 fa = u2f2(a0), fb = u2f2(a1);
                const float s = (fa.x + fa.y) + (fb.x + fb.y) + bias2;
                h2s[((size_t)p * Kn + k) * C2 + c2] = fmaxf(s, 0.0f);
            }
        }
    }
    __syncthreads();

    // ---- layer 3 + max over k ----
    // q = tid>>1 owns channels {q, q+128}; r = tid&1 owns half-slice [64r, 64r+64).
    // Chunk order rotated by 4*r so the pair's concurrent 16B LDS hit disjoint banks.
    {
        const int q = tid >> 1;            // 0..127
        const int r = tid & 1;
        const int sbase = r * 16;          // ull2 offset of this half (16 x 16B = 64 floats)
        const int rot   = r * 4;

        ulonglong2 w3a[16], w3b[16];
        const ulonglong2* rowA = reinterpret_cast<const ulonglong2*>(W3 + (size_t)q * C2);
        const ulonglong2* rowB = reinterpret_cast<const ulonglong2*>(W3 + (size_t)(q + 128) * C2);
#pragma unroll
        for (int i = 0; i < 16; i++) {
            const int c = (i + rot) & 15;
            w3a[i] = rowA[sbase + c];
            w3b[i] = rowB[sbase + c];
        }
        const float bias = __ldg(&b3[q + 128 * r]);

#pragma unroll 1
        for (int p = 0; p < P; p++) {
            const float* hp = h2s + (size_t)p * Kn * C2;
            float vmA = -1e30f, vmB = -1e30f;

#pragma unroll 1
            for (int k = 0; k < Kn; k++) {
                const ulonglong2* hrow = reinterpret_cast<const ulonglong2*>(hp + (size_t)k * C2);
                ulonglong2 hv[16];
#pragma unroll
                for (int i = 0; i < 16; i++)
                    hv[i] = hrow[sbase + ((i + rot) & 15)];   // 2 bcast addrs, disjoint banks

                unsigned long long a0 = 0ull, a1 = 0ull, c0 = 0ull, c1 = 0ull;
#pragma unroll
                for (int i = 0; i < 16; i++) {
                    a0 = pfma2(hv[i].x, w3a[i].x, a0);
                    a1 = pfma2(hv[i].y, w3a[i].y, a1);
                    c0 = pfma2(hv[i].x, w3b[i].x, c0);
                    c1 = pfma2(hv[i].y, w3b[i].y, c1);
                }
                const float2 fa0 = u2f2(a0), fa1 = u2f2(a1);
                const float2 fc0 = u2f2(c0), fc1 = u2f2(c1);
                float sA = (fa0.x + fa0.y) + (fa1.x + fa1.y);
                float sB = (fc0.x + fc0.y) + (fc1.x + fc1.y);
                sA += __shfl_xor_sync(0xffffffffu, sA, 1);    // pair-reduce: full dot
                sB += __shfl_xor_sync(0xffffffffu, sB, 1);
                vmA = fmaxf(vmA, sA);
                vmB = fmaxf(vmB, sB);
            }
            // lane r=0 writes channel q, lane r=1 writes channel q+128
            const float v = (r == 0) ? vmA : vmB;
            out[(size_t)(bm0 + p) * C3 + q + 128 * r] = v + bias;
        }
    }
}

extern "C" void kernel_launch(void* const* d_in, const int* in_sizes, int n_in,
                              void* d_out, int out_size) {
    (void)in_sizes; (void)n_in; (void)out_size;
    const float* xyz     = (const float*)d_in[0];
    const float* centers = (const float*)d_in[1];
    const int*   idx     = (const int*)  d_in[2];
    const float* W1      = (const float*)d_in[3];
    const float* b1      = (const float*)d_in[4];
    const float* W2      = (const float*)d_in[5];
    const float* b2      = (const float*)d_in[6];
    const float* W3      = (const float*)d_in[7];
    const float* b3      = (const float*)d_in[8];
    float*       out     = (float*)d_out;

    static bool attr_done = false;
    if (!attr_done) {
        cudaFuncSetAttribute(patch_embed_kernel,
                             cudaFuncAttributeMaxDynamicSharedMemorySize, SMEM_BYTES);
        attr_done = true;
    }

    patch_embed_kernel<<<(Bb * Mc) / P, 256, SMEM_BYTES>>>(xyz, centers, idx,
                                                           W1, b1, W2, b2, W3, b3, out);
}

// round 6
// speedup vs baseline: 6.5010x; 2.6670x over previous
#include <cuda_runtime.h>
#include <cstdint>

// PatchEmbed round 6: warp-level mma.sync tf32 (compute_103-safe; tcgen05 is
// blocked by the harness's virtual arch). Persistent CTAs; weights resident as
// mma B-fragments in registers; activations split hi/lo tf32 (2-pass mma) for
// accuracy; h1/h2 in padded smem planes (conflict-free A-fragment LDS).

constexpr int Bb = 8, Nn = 16384, Mc = 2048, Kn = 32;
constexpr int C1 = 64, C2 = 128, C3 = 256;
constexpr int P  = 4;                       // points/group -> M = 128 rows (pk)
constexpr int NGRP = Bb * Mc / P;           // 4096
constexpr int GRID = 152;
constexpr int THREADS = 256;

constexpr int S1 = 68;                      // h1 row stride (floats), conflict-free
constexpr int S2 = 132;                     // h2 row stride
constexpr int H1PLANE = 128 * S1;           // floats per plane
constexpr int H2PLANE = 128 * S2;
constexpr uint32_t SMEM_BYTES = (2 * H1PLANE + 2 * H2PLANE) * 4;   // 204800 B

__device__ __forceinline__ uint32_t tf32r(float f) {
    uint32_t u;
    asm("cvt.rna.tf32.f32 %0, %1;" : "=r"(u) : "f"(f));
    return u;
}

__device__ __forceinline__ void mma8(float& d0, float& d1, float& d2, float& d3,
                                     uint32_t a0, uint32_t a1, uint32_t a2, uint32_t a3,
                                     uint32_t b0, uint32_t b1) {
    asm volatile(
        "mma.sync.aligned.m16n8k8.row.col.f32.tf32.tf32.f32 "
        "{%0,%1,%2,%3},{%4,%5,%6,%7},{%8,%9},{%0,%1,%2,%3};"
        : "+f"(d0), "+f"(d1), "+f"(d2), "+f"(d3)
        : "r"(a0), "r"(a1), "r"(a2), "r"(a3), "r"(b0), "r"(b1));
}

__global__ __launch_bounds__(THREADS, 1)
void pe_mma(const float* __restrict__ xyz,
            const float* __restrict__ centers,
            const int*   __restrict__ idx,
            const float* __restrict__ W1, const float* __restrict__ b1,
            const float* __restrict__ W2, const float* __restrict__ b2,
            const float* __restrict__ W3, const float* __restrict__ b3,
            float* __restrict__ out) {
    extern __shared__ float smf[];
    float* h1h = smf;                            // [128][S1] tf32-hi
    float* h1l = smf + H1PLANE;                  // tf32-lo
    float* h2h = smf + 2 * H1PLANE;              // [128][S2]
    float* h2l = h2h + H2PLANE;
    const uint32_t* h1hu = reinterpret_cast<const uint32_t*>(h1h);
    const uint32_t* h1lu = reinterpret_cast<const uint32_t*>(h1l);
    const uint32_t* h2hu = reinterpret_cast<const uint32_t*>(h2h);
    const uint32_t* h2lu = reinterpret_cast<const uint32_t*>(h2l);

    __shared__ float  ls[128][3];                // local coords (fp32 exact)
    __shared__ float4 wb1[64];                   // {w0,w1,w2,bias}

    const int tid  = threadIdx.x;
    const int warp = tid >> 5;
    const int lane = tid & 31;
    const int g    = lane >> 2;                  // mma groupID
    const int t    = lane & 3;                   // mma threadID_in_group

    // ---- one-time: W1/b1 table ----
    if (tid < 64)
        wb1[tid] = make_float4(__ldg(&W1[tid * 3 + 0]), __ldg(&W1[tid * 3 + 1]),
                               __ldg(&W1[tid * 3 + 2]), __ldg(&b1[tid]));

    // ---- one-time: resident weight B-fragments (B[k][n] = W[n][k], tf32) ----
    const int c2b = warp * 16;                   // GEMM2 n-strip (16 c2)
    uint32_t b2f[8][2][2];
#pragma unroll
    for (int k = 0; k < 8; k++)
#pragma unroll
        for (int n = 0; n < 2; n++) {
            const int row = c2b + n * 8 + g;
            b2f[k][n][0] = tf32r(__ldg(&W2[row * C1 + k * 8 + t]));
            b2f[k][n][1] = tf32r(__ldg(&W2[row * C1 + k * 8 + t + 4]));
        }
    const int chb = warp * 32;                   // GEMM3 n-strip (32 ch)
    uint32_t b3f[16][4][2];
#pragma unroll
    for (int k = 0; k < 16; k++)
#pragma unroll
        for (int n = 0; n < 4; n++) {
            const int row = chb + n * 8 + g;
            b3f[k][n][0] = tf32r(__ldg(&W3[row * C2 + k * 8 + t]));
            b3f[k][n][1] = tf32r(__ldg(&W3[row * C2 + k * 8 + t + 4]));
        }

    // ---- persistent group loop ----
    for (int grp = blockIdx.x; grp < NGRP; grp += GRID) {
        const int bm0 = grp * P;
        const int b   = bm0 >> 11;

        __syncthreads();                         // prev GEMM3 done before reuse

        // -- gather + center subtract --
        if (tid < P * Kn) {
            const int bm = bm0 + (tid >> 5);
            const int id = __ldg(&idx[(size_t)bm * Kn + (tid & 31)]);
            const float* xp = xyz + ((size_t)b * Nn + id) * 3;
            const float* cp = centers + (size_t)bm * 3;
            ls[tid][0] = __ldg(xp + 0) - __ldg(cp + 0);
            ls[tid][1] = __ldg(xp + 1) - __ldg(cp + 1);
            ls[tid][2] = __ldg(xp + 2) - __ldg(cp + 2);
        }
        __syncthreads();

        // -- layer 1: h1 = relu(W1.local + b1), split hi/lo tf32 --
        {
            const int row = tid >> 1;
            const int cb  = (tid & 1) * 32;
            const float lx = ls[row][0], ly = ls[row][1], lz = ls[row][2];
            uint32_t* ph = reinterpret_cast<uint32_t*>(h1h + row * S1 + cb);
            uint32_t* pl = reinterpret_cast<uint32_t*>(h1l + row * S1 + cb);
#pragma unroll
            for (int j4 = 0; j4 < 8; j4++) {
                uint4 hv, lv;
#pragma unroll
                for (int i = 0; i < 4; i++) {
                    const float4 w = wb1[cb + j4 * 4 + i];
                    const float v = fmaxf(fmaf(w.x, lx, fmaf(w.y, ly, fmaf(w.z, lz, w.w))), 0.f);
                    const uint32_t hb = tf32r(v);
                    const uint32_t lb = tf32r(v - __uint_as_float(hb));
                    (&hv.x)[i] = hb;
                    (&lv.x)[i] = lb;
                }
                *reinterpret_cast<uint4*>(ph + j4 * 4) = hv;
                *reinterpret_cast<uint4*>(pl + j4 * 4) = lv;
            }
        }
        __syncthreads();

        // -- GEMM2: D2[pk][c2] = h1 @ W2^T (split A, resident B), + epi2 -> h2 --
#pragma unroll 1
        for (int pass = 0; pass < 2; pass++) {
            const int mb0 = pass * 64;
            float acc[4][2][4];
#pragma unroll
            for (int mt = 0; mt < 4; mt++)
#pragma unroll
                for (int n = 0; n < 2; n++)
#pragma unroll
                    for (int i = 0; i < 4; i++) acc[mt][n][i] = 0.f;

#pragma unroll
            for (int mt = 0; mt < 4; mt++) {
                const int r0 = (mb0 + mt * 16 + g) * S1;
#pragma unroll
                for (int k = 0; k < 8; k++) {
                    const int co = k * 8 + t;
                    const uint32_t ah0 = h1hu[r0 + co],          ah2 = h1hu[r0 + co + 4];
                    const uint32_t ah1 = h1hu[r0 + 8 * S1 + co], ah3 = h1hu[r0 + 8 * S1 + co + 4];
                    const uint32_t al0 = h1lu[r0 + co],          al2 = h1lu[r0 + co + 4];
                    const uint32_t al1 = h1lu[r0 + 8 * S1 + co], al3 = h1lu[r0 + 8 * S1 + co + 4];
#pragma unroll
                    for (int n = 0; n < 2; n++) {
                        mma8(acc[mt][n][0], acc[mt][n][1], acc[mt][n][2], acc[mt][n][3],
                             ah0, ah1, ah2, ah3, b2f[k][n][0], b2f[k][n][1]);
                        mma8(acc[mt][n][0], acc[mt][n][1], acc[mt][n][2], acc[mt][n][3],
                             al0, al1, al2, al3, b2f[k][n][0], b2f[k][n][1]);
                    }
                }
            }
            // epi2: +bias, relu, split hi/lo tf32, store to h2 planes
#pragma unroll
            for (int mt = 0; mt < 4; mt++) {
                const int r0 = mb0 + mt * 16 + g;
#pragma unroll
                for (int n = 0; n < 2; n++) {
                    const int c = c2b + n * 8 + 2 * t;
                    const float bb0 = __ldg(&b2[c]), bb1 = __ldg(&b2[c + 1]);
                    const float v00 = fmaxf(acc[mt][n][0] + bb0, 0.f);
                    const float v01 = fmaxf(acc[mt][n][1] + bb1, 0.f);
                    const float v10 = fmaxf(acc[mt][n][2] + bb0, 0.f);
                    const float v11 = fmaxf(acc[mt][n][3] + bb1, 0.f);
                    const uint32_t h00 = tf32r(v00), h01 = tf32r(v01);
                    const uint32_t h10 = tf32r(v10), h11 = tf32r(v11);
                    float2 hv0 = {__uint_as_float(h00), __uint_as_float(h01)};
                    float2 hv1 = {__uint_as_float(h10), __uint_as_float(h11)};
                    float2 lv0 = {__uint_as_float(tf32r(v00 - hv0.x)),
                                  __uint_as_float(tf32r(v01 - hv0.y))};
                    float2 lv1 = {__uint_as_float(tf32r(v10 - hv1.x)),
                                  __uint_as_float(tf32r(v11 - hv1.y))};
                    *reinterpret_cast<float2*>(h2h + r0 * S2 + c)       = hv0;
                    *reinterpret_cast<float2*>(h2h + (r0 + 8) * S2 + c) = hv1;
                    *reinterpret_cast<float2*>(h2l + r0 * S2 + c)       = lv0;
                    *reinterpret_cast<float2*>(h2l + (r0 + 8) * S2 + c) = lv1;
                }
            }
        }
        __syncthreads();

        // -- GEMM3: D3[pk][ch] = h2 @ W3^T (split A, resident B) + max epilogue --
#pragma unroll 1
        for (int p = 0; p < P; p++) {
            float vme[4], vmo[4];
#pragma unroll
            for (int n = 0; n < 4; n++) { vme[n] = -1e30f; vmo[n] = -1e30f; }

            float acc[4][4];
#pragma unroll 1
            for (int hmt = 0; hmt < 2; hmt++) {          // m-tiles 2p, 2p+1
                const int r0 = (p * 32 + hmt * 16 + g) * S2;
#pragma unroll
                for (int n = 0; n < 4; n++)
#pragma unroll
                    for (int i = 0; i < 4; i++) acc[n][i] = 0.f;

#pragma unroll
                for (int k = 0; k < 16; k++) {
                    const int co = k * 8 + t;
                    const uint32_t ah0 = h2hu[r0 + co],          ah2 = h2hu[r0 + co + 4];
                    const uint32_t ah1 = h2hu[r0 + 8 * S2 + co], ah3 = h2hu[r0 + 8 * S2 + co + 4];
                    const uint32_t al0 = h2lu[r0 + co],          al2 = h2lu[r0 + co + 4];
                    const uint32_t al1 = h2lu[r0 + 8 * S2 + co], al3 = h2lu[r0 + 8 * S2 + co + 4];
#pragma unroll
                    for (int n = 0; n < 4; n++) {
                        mma8(acc[n][0], acc[n][1], acc[n][2], acc[n][3],
                             ah0, ah1, ah2, ah3, b3f[k][n][0], b3f[k][n][1]);
                        mma8(acc[n][0], acc[n][1], acc[n][2], acc[n][3],
                             al0, al1, al2, al3, b3f[k][n][0], b3f[k][n][1]);
                    }
                }
#pragma unroll
                for (int n = 0; n < 4; n++) {
                    vme[n] = fmaxf(vme[n], fmaxf(acc[n][0], acc[n][2]));
                    vmo[n] = fmaxf(vmo[n], fmaxf(acc[n][1], acc[n][3]));
                }
            }
            // reduce over the 8 row-groups (lanes strided by 4), then write
#pragma unroll
            for (int n = 0; n < 4; n++) {
                float ve = vme[n], vo = vmo[n];
#pragma unroll
                for (int s = 4; s < 32; s <<= 1) {
                    ve = fmaxf(ve, __shfl_xor_sync(0xffffffffu, ve, s));
                    vo = fmaxf(vo, __shfl_xor_sync(0xffffffffu, vo, s));
                }
                if (lane < 4) {
                    const int ch = chb + n * 8 + 2 * lane;
                    float2 o = {ve + __ldg(&b3[ch]), vo + __ldg(&b3[ch + 1])};
                    *reinterpret_cast<float2*>(out + (size_t)(bm0 + p) * C3 + ch) = o;
                }
            }
        }
    }
}

extern "C" void kernel_launch(void* const* d_in, const int* in_sizes, int n_in,
                              void* d_out, int out_size) {
    (void)in_sizes; (void)n_in; (void)out_size;
    const float* xyz     = (const float*)d_in[0];
    const float* centers = (const float*)d_in[1];
    const int*   idx     = (const int*)  d_in[2];
    const float* W1      = (const float*)d_in[3];
    const float* b1      = (const float*)d_in[4];
    const float* W2      = (const float*)d_in[5];
    const float* b2      = (const float*)d_in[6];
    const float* W3      = (const float*)d_in[7];
    const float* b3      = (const float*)d_in[8];
    float*       out     = (float*)d_out;

    cudaFuncSetAttribute(pe_mma, cudaFuncAttributeMaxDynamicSharedMemorySize, SMEM_BYTES);
    pe_mma<<<GRID, THREADS, SMEM_BYTES>>>(xyz, centers, idx,
                                          W1, b1, W2, b2, W3, b3, out);
}

// round 9
// speedup vs baseline: 11.4676x; 1.7640x over previous
#include <cuda_runtime.h>
#include <cstdint>

// PatchEmbed round 8: R7 with the batch-index fix (b = bm0 >> 11, bm0 is a
// POINT index). Single-pass tf32 mma.sync, P=8 points/group (M=256 rows),
// persistent 152 CTAs, weights resident as B-fragments in registers,
// h1/h2 in padded conflict-free smem.

constexpr int Bb = 8, Nn = 16384, Mc = 2048, Kn = 32;
constexpr int C1 = 64, C2 = 128, C3 = 256;
constexpr int P  = 8;                       // points/group -> M = 256 rows (pk)
constexpr int NGRP = Bb * Mc / P;           // 2048
constexpr int GRID = 152;
constexpr int THREADS = 256;
constexpr int MROWS = P * Kn;               // 256

constexpr int S1 = 68;                      // h1 row stride (floats)
constexpr int S2 = 132;                     // h2 row stride
constexpr int H1PLANE = MROWS * S1;         // 17408 floats
constexpr int H2PLANE = MROWS * S2;         // 33792 floats
constexpr uint32_t SMEM_BYTES = (H1PLANE + H2PLANE) * 4;   // 204800 B

__device__ __forceinline__ uint32_t tf32r(float f) {
    uint32_t u;
    asm("cvt.rna.tf32.f32 %0, %1;" : "=r"(u) : "f"(f));
    return u;
}

__device__ __forceinline__ void mma8(float& d0, float& d1, float& d2, float& d3,
                                     uint32_t a0, uint32_t a1, uint32_t a2, uint32_t a3,
                                     uint32_t b0, uint32_t b1) {
    asm volatile(
        "mma.sync.aligned.m16n8k8.row.col.f32.tf32.tf32.f32 "
        "{%0,%1,%2,%3},{%4,%5,%6,%7},{%8,%9},{%0,%1,%2,%3};"
        : "+f"(d0), "+f"(d1), "+f"(d2), "+f"(d3)
        : "r"(a0), "r"(a1), "r"(a2), "r"(a3), "r"(b0), "r"(b1));
}

__global__ __launch_bounds__(THREADS, 1)
void pe_mma(const float* __restrict__ xyz,
            const float* __restrict__ centers,
            const int*   __restrict__ idx,
            const float* __restrict__ W1, const float* __restrict__ b1,
            const float* __restrict__ W2, const float* __restrict__ b2,
            const float* __restrict__ W3, const float* __restrict__ b3,
            float* __restrict__ out) {
    extern __shared__ float smf[];
    float* h1 = smf;                              // [256][S1] tf32
    float* h2 = smf + H1PLANE;                    // [256][S2] tf32
    const uint32_t* h1u = reinterpret_cast<const uint32_t*>(h1);
    const uint32_t* h2u = reinterpret_cast<const uint32_t*>(h2);

    __shared__ float  ls[MROWS][3];               // local coords (fp32 exact)
    __shared__ float4 wb1[64];                    // {w0,w1,w2,bias}

    const int tid  = threadIdx.x;
    const int warp = tid >> 5;
    const int lane = tid & 31;
    const int g    = lane >> 2;                   // mma groupID
    const int t    = lane & 3;                    // mma threadID_in_group

    // ---- one-time: W1/b1 table ----
    if (tid < 64)
        wb1[tid] = make_float4(__ldg(&W1[tid * 3 + 0]), __ldg(&W1[tid * 3 + 1]),
                               __ldg(&W1[tid * 3 + 2]), __ldg(&b1[tid]));

    // ---- one-time: resident weight B-fragments (B[k][n] = W[n][k], tf32) ----
    const int c2b = warp * 16;                    // GEMM2 n-strip (16 c2)
    uint32_t b2f[8][2][2];
#pragma unroll
    for (int k = 0; k < 8; k++)
#pragma unroll
        for (int n = 0; n < 2; n++) {
            const int row = c2b + n * 8 + g;
            b2f[k][n][0] = tf32r(__ldg(&W2[row * C1 + k * 8 + t]));
            b2f[k][n][1] = tf32r(__ldg(&W2[row * C1 + k * 8 + t + 4]));
        }
    const int chb = warp * 32;                    // GEMM3 n-strip (32 ch)
    uint32_t b3f[16][4][2];
#pragma unroll
    for (int k = 0; k < 16; k++)
#pragma unroll
        for (int n = 0; n < 4; n++) {
            const int row = chb + n * 8 + g;
            b3f[k][n][0] = tf32r(__ldg(&W3[row * C2 + k * 8 + t]));
            b3f[k][n][1] = tf32r(__ldg(&W3[row * C2 + k * 8 + t + 4]));
        }
    // hoisted epilogue-2 biases (depend only on warp/t)
    float bias2[2][2];
#pragma unroll
    for (int n = 0; n < 2; n++) {
        bias2[n][0] = __ldg(&b2[c2b + n * 8 + 2 * t]);
        bias2[n][1] = __ldg(&b2[c2b + n * 8 + 2 * t + 1]);
    }

    // ---- persistent group loop ----
    for (int grp = blockIdx.x; grp < NGRP; grp += GRID) {
        const int bm0 = grp * P;                  // POINT index of first point
        const int b   = bm0 >> 11;                // batch = bm0 / Mc  (FIXED)

        __syncthreads();                          // prev GEMM3 reads done

        // -- gather + center subtract (256 threads, one (p,k) each) --
        {
            const int bm = bm0 + (tid >> 5);
            const int id = __ldg(&idx[(size_t)bm * Kn + (tid & 31)]);
            const float* xp = xyz + ((size_t)b * Nn + id) * 3;
            const float* cp = centers + (size_t)bm * 3;
            ls[tid][0] = __ldg(xp + 0) - __ldg(cp + 0);
            ls[tid][1] = __ldg(xp + 1) - __ldg(cp + 1);
            ls[tid][2] = __ldg(xp + 2) - __ldg(cp + 2);
        }
        __syncthreads();

        // -- layer 1: h1[row] = relu(W1.local + b1) -> tf32 (rotated stores) --
        {
            const int row = tid;
            const float lx = ls[row][0], ly = ls[row][1], lz = ls[row][2];
            uint32_t* ph = reinterpret_cast<uint32_t*>(h1 + row * S1);
            const int rot = lane >> 3;            // 0..3
#pragma unroll
            for (int j = 0; j < 16; j++) {
                const int c4 = (rot + j) & 15;    // uint4 slot
                uint4 o;
#pragma unroll
                for (int i = 0; i < 4; i++) {
                    const float4 w = wb1[c4 * 4 + i];
                    (&o.x)[i] = tf32r(fmaxf(fmaf(w.x, lx, fmaf(w.y, ly, fmaf(w.z, lz, w.w))), 0.f));
                }
                *reinterpret_cast<uint4*>(ph + c4 * 4) = o;
            }
        }
        __syncthreads();

        // -- GEMM2: D2[pk][c2] = h1 @ W2^T (M=256 in 4 passes of 64), epi2 -> h2 --
#pragma unroll 1
        for (int pass = 0; pass < 4; pass++) {
            const int mb0 = pass * 64;
            float acc[4][2][4];
#pragma unroll
            for (int mt = 0; mt < 4; mt++)
#pragma unroll
                for (int n = 0; n < 2; n++)
#pragma unroll
                    for (int i = 0; i < 4; i++) acc[mt][n][i] = 0.f;

#pragma unroll
            for (int mt = 0; mt < 4; mt++) {
                const int r0 = (mb0 + mt * 16 + g) * S1;
#pragma unroll
                for (int k = 0; k < 8; k++) {
                    const int co = k * 8 + t;
                    const uint32_t a0 = h1u[r0 + co],          a2 = h1u[r0 + co + 4];
                    const uint32_t a1 = h1u[r0 + 8 * S1 + co], a3 = h1u[r0 + 8 * S1 + co + 4];
#pragma unroll
                    for (int n = 0; n < 2; n++)
                        mma8(acc[mt][n][0], acc[mt][n][1], acc[mt][n][2], acc[mt][n][3],
                             a0, a1, a2, a3, b2f[k][n][0], b2f[k][n][1]);
                }
            }
            // epi2: +bias, relu, tf32, store
#pragma unroll
            for (int mt = 0; mt < 4; mt++) {
                const int r0 = mb0 + mt * 16 + g;
#pragma unroll
                for (int n = 0; n < 2; n++) {
                    const int c = c2b + n * 8 + 2 * t;
                    float2 v0, v1;
                    v0.x = __uint_as_float(tf32r(fmaxf(acc[mt][n][0] + bias2[n][0], 0.f)));
                    v0.y = __uint_as_float(tf32r(fmaxf(acc[mt][n][1] + bias2[n][1], 0.f)));
                    v1.x = __uint_as_float(tf32r(fmaxf(acc[mt][n][2] + bias2[n][0], 0.f)));
                    v1.y = __uint_as_float(tf32r(fmaxf(acc[mt][n][3] + bias2[n][1], 0.f)));
                    *reinterpret_cast<float2*>(h2 + r0 * S2 + c)       = v0;
                    *reinterpret_cast<float2*>(h2 + (r0 + 8) * S2 + c) = v1;
                }
            }
        }
        __syncthreads();

        // -- GEMM3: D3[pk][ch] = h2 @ W3^T + max-over-k epilogue --
#pragma unroll 1
        for (int p = 0; p < P; p++) {
            float vme[4], vmo[4];
#pragma unroll
            for (int n = 0; n < 4; n++) { vme[n] = -1e30f; vmo[n] = -1e30f; }

            float acc[4][4];
#pragma unroll 1
            for (int hmt = 0; hmt < 2; hmt++) {           // m-tiles for this p
                const int r0 = (p * 32 + hmt * 16 + g) * S2;
#pragma unroll
                for (int n = 0; n < 4; n++)
#pragma unroll
                    for (int i = 0; i < 4; i++) acc[n][i] = 0.f;

#pragma unroll
                for (int k = 0; k < 16; k++) {
                    const int co = k * 8 + t;
                    const uint32_t a0 = h2u[r0 + co],          a2 = h2u[r0 + co + 4];
                    const uint32_t a1 = h2u[r0 + 8 * S2 + co], a3 = h2u[r0 + 8 * S2 + co + 4];
#pragma unroll
                    for (int n = 0; n < 4; n++)
                        mma8(acc[n][0], acc[n][1], acc[n][2], acc[n][3],
                             a0, a1, a2, a3, b3f[k][n][0], b3f[k][n][1]);
                }
#pragma unroll
                for (int n = 0; n < 4; n++) {
                    vme[n] = fmaxf(vme[n], fmaxf(acc[n][0], acc[n][2]));
                    vmo[n] = fmaxf(vmo[n], fmaxf(acc[n][1], acc[n][3]));
                }
            }
            // reduce across lanes (row-groups strided by 4) and store
#pragma unroll
            for (int n = 0; n < 4; n++) {
                float ve = vme[n], vo = vmo[n];
#pragma unroll
                for (int s = 4; s < 32; s <<= 1) {
                    ve = fmaxf(ve, __shfl_xor_sync(0xffffffffu, ve, s));
                    vo = fmaxf(vo, __shfl_xor_sync(0xffffffffu, vo, s));
                }
                if (lane < 4) {
                    const int ch = chb + n * 8 + 2 * lane;
                    float2 o = {ve + __ldg(&b3[ch]), vo + __ldg(&b3[ch + 1])};
                    *reinterpret_cast<float2*>(out + (size_t)(bm0 + p) * C3 + ch) = o;
                }
            }
        }
    }
}

extern "C" void kernel_launch(void* const* d_in, const int* in_sizes, int n_in,
                              void* d_out, int out_size) {
    (void)in_sizes; (void)n_in; (void)out_size;
    const float* xyz     = (const float*)d_in[0];
    const float* centers = (const float*)d_in[1];
    const int*   idx     = (const int*)  d_in[2];
    const float* W1      = (const float*)d_in[3];
    const float* b1      = (const float*)d_in[4];
    const float* W2      = (const float*)d_in[5];
    const float* b2      = (const float*)d_in[6];
    const float* W3      = (const float*)d_in[7];
    const float* b3      = (const float*)d_in[8];
    float*       out     = (float*)d_out;

    cudaFuncSetAttribute(pe_mma, cudaFuncAttributeMaxDynamicSharedMemorySize, SMEM_BYTES);
    pe_mma<<<GRID, THREADS, SMEM_BYTES>>>(xyz, centers, idx,
                                          W1, b1, W2, b2, W3, b3, out);
}

// round 10
// speedup vs baseline: 18.2966x; 1.5955x over previous
#include <cuda_runtime.h>
#include <cuda_fp16.h>
#include <cstdint>

// PatchEmbed round 10: fp16 mma.sync m16n8k16 (f32 accumulate).
// fp16 mantissa == tf32 mantissa (10 bits) -> same accuracy as R8, but
// half the mma count AND half the smem A-fragment bytes (the two measured
// bottlenecks of R8: tensor 56%, L1 53%). Gather fused into layer1 (same
// thread), next-group gather prefetched under GEMM2, 2 syncs/group.

constexpr int Bb = 8, Nn = 16384, Mc = 2048, Kn = 32;
constexpr int C1 = 64, C2 = 128, C3 = 256;
constexpr int P  = 8;                        // points/group -> M = 256 rows
constexpr int NGRP = Bb * Mc / P;            // 2048
constexpr int GRID = 152;
constexpr int THREADS = 256;
constexpr int MROWS = P * Kn;                // 256

constexpr int S1W = 36;                      // h1 row stride, 32-bit words (32 data + 4 pad)
constexpr int S2W = 68;                      // h2 row stride, words (64 data + 4 pad)
constexpr int H1W = MROWS * S1W;             // 9216 words
constexpr int H2W = MROWS * S2W;             // 17408 words
constexpr uint32_t SMEM_BYTES = (H1W + H2W) * 4;   // 106496 B

__device__ __forceinline__ uint32_t packh2(float lo, float hi) {
    __half2 h = __floats2half2_rn(lo, hi);   // .x = lo (lower 16 bits)
    return *reinterpret_cast<uint32_t*>(&h);
}

__device__ __forceinline__ void mma16(float& d0, float& d1, float& d2, float& d3,
                                      uint32_t a0, uint32_t a1, uint32_t a2, uint32_t a3,
                                      uint32_t b0, uint32_t b1) {
    asm volatile(
        "mma.sync.aligned.m16n8k16.row.col.f32.f16.f16.f32 "
        "{%0,%1,%2,%3},{%4,%5,%6,%7},{%8,%9},{%0,%1,%2,%3};"
        : "+f"(d0), "+f"(d1), "+f"(d2), "+f"(d3)
        : "r"(a0), "r"(a1), "r"(a2), "r"(a3), "r"(b0), "r"(b1));
}

__global__ __launch_bounds__(THREADS, 1)
void pe_mma(const float* __restrict__ xyz,
            const float* __restrict__ centers,
            const int*   __restrict__ idx,
            const float* __restrict__ W1, const float* __restrict__ b1,
            const float* __restrict__ W2, const float* __restrict__ b2,
            const float* __restrict__ W3, const float* __restrict__ b3,
            float* __restrict__ out) {
    extern __shared__ uint32_t smw[];
    uint32_t* h1u = smw;                     // [256][S1W] f16x2 words
    uint32_t* h2u = smw + H1W;               // [256][S2W]

    __shared__ float4 wb1[64];               // {w0,w1,w2,bias} fp32

    const int tid  = threadIdx.x;
    const int warp = tid >> 5;
    const int lane = tid & 31;
    const int g    = lane >> 2;              // mma groupID (row within tile)
    const int t    = lane & 3;               // threadID_in_group

    // ---- one-time: W1/b1 table ----
    if (tid < 64)
        wb1[tid] = make_float4(__ldg(&W1[tid * 3 + 0]), __ldg(&W1[tid * 3 + 1]),
                               __ldg(&W1[tid * 3 + 2]), __ldg(&b1[tid]));

    // ---- one-time: resident f16 weight B-fragments (B[k][n] = W[n][k]) ----
    const int c2b = warp * 16;               // GEMM2 n-strip
    uint32_t b2f[4][2][2];
#pragma unroll
    for (int kc = 0; kc < 4; kc++)
#pragma unroll
        for (int n = 0; n < 2; n++) {
            const int row = c2b + n * 8 + g;
            const float* wr = W2 + (size_t)row * C1 + kc * 16;
            b2f[kc][n][0] = packh2(__ldg(wr + 2 * t),     __ldg(wr + 2 * t + 1));
            b2f[kc][n][1] = packh2(__ldg(wr + 2 * t + 8), __ldg(wr + 2 * t + 9));
        }
    const int chb = warp * 32;               // GEMM3 n-strip
    uint32_t b3f[8][4][2];
#pragma unroll
    for (int kc = 0; kc < 8; kc++)
#pragma unroll
        for (int n = 0; n < 4; n++) {
            const int row = chb + n * 8 + g;
            const float* wr = W3 + (size_t)row * C2 + kc * 16;
            b3f[kc][n][0] = packh2(__ldg(wr + 2 * t),     __ldg(wr + 2 * t + 1));
            b3f[kc][n][1] = packh2(__ldg(wr + 2 * t + 8), __ldg(wr + 2 * t + 9));
        }
    // hoisted epilogue-2 biases
    float bias2[2][2];
#pragma unroll
    for (int n = 0; n < 2; n++) {
        bias2[n][0] = __ldg(&b2[c2b + n * 8 + 2 * t]);
        bias2[n][1] = __ldg(&b2[c2b + n * 8 + 2 * t + 1]);
    }

    // ---- gather helper: thread owns row tid = (p = tid>>5, k = tid&31) ----
    auto gather = [&](int grp, float& lx, float& ly, float& lz) {
        const int bm0 = grp * P;
        const int b   = bm0 >> 11;           // batch = point/Mc
        const int bm  = bm0 + (tid >> 5);
        const int id  = __ldg(&idx[(size_t)bm * Kn + (tid & 31)]);
        const float* xp = xyz + ((size_t)b * Nn + id) * 3;
        const float* cp = centers + (size_t)bm * 3;
        lx = __ldg(xp + 0) - __ldg(cp + 0);
        ly = __ldg(xp + 1) - __ldg(cp + 1);
        lz = __ldg(xp + 2) - __ldg(cp + 2);
    };
    // layer1: compute 64 channels fp32, pack f16x2, 8x STS.128 (conflict-free)
    auto layer1 = [&](float lx, float ly, float lz) {
        uint32_t* ph = h1u + tid * S1W;
#pragma unroll
        for (int j4 = 0; j4 < 8; j4++) {
            uint4 o;
#pragma unroll
            for (int w = 0; w < 4; w++) {
                const int c0 = j4 * 8 + 2 * w;
                const float4 wa = wb1[c0];
                const float4 wb = wb1[c0 + 1];
                const float vlo = fmaxf(fmaf(wa.x, lx, fmaf(wa.y, ly, fmaf(wa.z, lz, wa.w))), 0.f);
                const float vhi = fmaxf(fmaf(wb.x, lx, fmaf(wb.y, ly, fmaf(wb.z, lz, wb.w))), 0.f);
                (&o.x)[w] = packh2(vlo, vhi);
            }
            *reinterpret_cast<uint4*>(ph + j4 * 4) = o;
        }
    };

    // ---- prologue: first group's h1 ----
    int grp = blockIdx.x;
    if (grp < NGRP) {
        float lx, ly, lz;
        gather(grp, lx, ly, lz);
        layer1(lx, ly, lz);
    }
    __syncthreads();

    // ---- persistent group loop ----
    for (; grp < NGRP; grp += GRID) {
        const int bm0 = grp * P;

        // prefetch next group's gather (latency hides under GEMM2)
        float nlx, nly, nlz;
        {
            int gn = grp + GRID;
            if (gn >= NGRP) gn = NGRP - 1;   // clamped, result unused on last iter
            gather(gn, nlx, nly, nlz);
        }

        // -- GEMM2: D2[pk][c2] = h1 @ W2^T (M=256 in 4 passes), epi2 -> h2 --
#pragma unroll 1
        for (int pass = 0; pass < 4; pass++) {
            const int mb0 = pass * 64;
            float acc[4][2][4];
#pragma unroll
            for (int mt = 0; mt < 4; mt++)
#pragma unroll
                for (int n = 0; n < 2; n++)
#pragma unroll
                    for (int i = 0; i < 4; i++) acc[mt][n][i] = 0.f;

#pragma unroll
            for (int mt = 0; mt < 4; mt++) {
                const int r0 = (mb0 + mt * 16 + g) * S1W;
                const int r1 = r0 + 8 * S1W;
#pragma unroll
                for (int kc = 0; kc < 4; kc++) {
                    const int co = kc * 8 + t;
                    const uint32_t a0 = h1u[r0 + co], a2 = h1u[r0 + co + 4];
                    const uint32_t a1 = h1u[r1 + co], a3 = h1u[r1 + co + 4];
#pragma unroll
                    for (int n = 0; n < 2; n++)
                        mma16(acc[mt][n][0], acc[mt][n][1], acc[mt][n][2], acc[mt][n][3],
                              a0, a1, a2, a3, b2f[kc][n][0], b2f[kc][n][1]);
                }
            }
            // epi2: +bias, relu, pack f16x2, store (words c/2 = warp*8 + n*4 + t)
#pragma unroll
            for (int mt = 0; mt < 4; mt++) {
                const int r0 = mb0 + mt * 16 + g;
#pragma unroll
                for (int n = 0; n < 2; n++) {
                    const int wcol = warp * 8 + n * 4 + t;
                    h2u[r0 * S2W + wcol] =
                        packh2(fmaxf(acc[mt][n][0] + bias2[n][0], 0.f),
                               fmaxf(acc[mt][n][1] + bias2[n][1], 0.f));
                    h2u[(r0 + 8) * S2W + wcol] =
                        packh2(fmaxf(acc[mt][n][2] + bias2[n][0], 0.f),
                               fmaxf(acc[mt][n][3] + bias2[n][1], 0.f));
                }
            }
        }
        __syncthreads();                     // h2 ready; h1 reads complete

        // -- GEMM3: D3[pk][ch] = h2 @ W3^T + max-over-k epilogue --
#pragma unroll 1
        for (int p = 0; p < P; p++) {
            float vme[4], vmo[4];
#pragma unroll
            for (int n = 0; n < 4; n++) { vme[n] = -1e30f; vmo[n] = -1e30f; }

            float acc[4][4];
#pragma unroll 1
            for (int hmt = 0; hmt < 2; hmt++) {
                const int r0 = (p * 32 + hmt * 16 + g) * S2W;
                const int r1 = r0 + 8 * S2W;
#pragma unroll
                for (int n = 0; n < 4; n++)
#pragma unroll
                    for (int i = 0; i < 4; i++) acc[n][i] = 0.f;

#pragma unroll
                for (int kc = 0; kc < 8; kc++) {
                    const int co = kc * 8 + t;
                    const uint32_t a0 = h2u[r0 + co], a2 = h2u[r0 + co + 4];
                    const uint32_t a1 = h2u[r1 + co], a3 = h2u[r1 + co + 4];
#pragma unroll
                    for (int n = 0; n < 4; n++)
                        mma16(acc[n][0], acc[n][1], acc[n][2], acc[n][3],
                              a0, a1, a2, a3, b3f[kc][n][0], b3f[kc][n][1]);
                }
#pragma unroll
                for (int n = 0; n < 4; n++) {
                    vme[n] = fmaxf(vme[n], fmaxf(acc[n][0], acc[n][2]));
                    vmo[n] = fmaxf(vmo[n], fmaxf(acc[n][1], acc[n][3]));
                }
            }
#pragma unroll
            for (int n = 0; n < 4; n++) {
                float ve = vme[n], vo = vmo[n];
#pragma unroll
                for (int s = 4; s < 32; s <<= 1) {
                    ve = fmaxf(ve, __shfl_xor_sync(0xffffffffu, ve, s));
                    vo = fmaxf(vo, __shfl_xor_sync(0xffffffffu, vo, s));
                }
                if (lane < 4) {
                    const int ch = chb + n * 8 + 2 * lane;
                    float2 o = {ve + __ldg(&b3[ch]), vo + __ldg(&b3[ch + 1])};
                    *reinterpret_cast<float2*>(out + (size_t)(bm0 + p) * C3 + ch) = o;
                }
            }
        }

        // -- layer1 for next group (h1 free since the sync above) --
        layer1(nlx, nly, nlz);
        __syncthreads();                     // h1 ready for next GEMM2
    }
}

extern "C" void kernel_launch(void* const* d_in, const int* in_sizes, int n_in,
                              void* d_out, int out_size) {
    (void)in_sizes; (void)n_in; (void)out_size;
    const float* xyz     = (const float*)d_in[0];
    const float* centers = (const float*)d_in[1];
    const int*   idx     = (const int*)  d_in[2];
    const float* W1      = (const float*)d_in[3];
    const float* b1      = (const float*)d_in[4];
    const float* W2      = (const float*)d_in[5];
    const float* b2      = (const float*)d_in[6];
    const float* W3      = (const float*)d_in[7];
    const float* b3      = (const float*)d_in[8];
    float*       out     = (float*)d_out;

    cudaFuncSetAttribute(pe_mma, cudaFuncAttributeMaxDynamicSharedMemorySize, SMEM_BYTES);
    pe_mma<<<GRID, THREADS, SMEM_BYTES>>>(xyz, centers, idx,
                                          W1, b1, W2, b2, W3, b3, out);
}